// round 1
// baseline (speedup 1.0000x reference)
#include <cuda_runtime.h>

#define PI2 6.28318530717958647692f

// Scratch (device globals — no allocation allowed).
// g_xft: [mode(512)][b*32+i(1024)] complex
// g_wt : [mode(512)][i*32+o(1024)] complex
// g_oft: [b*32+o(1024)][mode(512)] complex
static __device__ float2 g_xft[512 * 1024];
static __device__ float2 g_wt [512 * 1024];
static __device__ float2 g_oft[1024 * 512];

// ---------------------------------------------------------------------------
// K0: transpose weights [i][o][m][ky] -> mode-major [mk][i*32+o] complex
// ---------------------------------------------------------------------------
__global__ void __launch_bounds__(256) k0_wt(const float* __restrict__ wr,
                                             const float* __restrict__ wi) {
    int tid = blockIdx.x * 256 + threadIdx.x;   // 524288 total
    int mk = tid >> 10;          // m*16+ky
    int io = tid & 1023;         // i*32+o
    g_wt[tid] = make_float2(wr[io * 512 + mk], wi[io * 512 + mk]);
}

// ---------------------------------------------------------------------------
// K1: forward truncated DFT. One block per (b,i).
//   stage1: y[h,ky]  = sum_w  x[h,w]  * e^{-2pi i ky w / 128}   (ky = 0..15)
//   stage2: xft[m,ky]= sum_h  y[h,ky] * e^{-2pi i kx h / 128}   (kx = m<16?m:96+m)
//   scaled by 1/128 (ortho forward)
// ---------------------------------------------------------------------------
__global__ void __launch_bounds__(256) k1_forward(const float* __restrict__ x) {
    __shared__ __align__(16) float2 tw1[2048];   // e^{-2pi i w*ky/128}, [w][ky]
    __shared__ float2 Tg[128];                   // (cos, sin)(+2pi p/128)
    __shared__ float2 ys[128 * 17];              // y[h][ky], stride 17 (bank pad)

    int t  = threadIdx.x;
    int bi = blockIdx.x;   // b*32+i

    for (int p = t; p < 128; p += 256) {
        float s, c;
        sincosf(PI2 * (float)p * (1.0f / 128.0f), &s, &c);
        Tg[p] = make_float2(c, s);
    }
    __syncthreads();
    for (int idx = t; idx < 2048; idx += 256) {
        int w = idx >> 4, ky = idx & 15;
        float2 g = Tg[(w * ky) & 127];
        tw1[idx] = make_float2(g.x, -g.y);
    }
    __syncthreads();

    // ---- stage 1: thread owns (h = t>>1, 8 ky values) ----
    int h   = t >> 1;
    int kyh = (t & 1) * 8;
    const float4* xr4 = (const float4*)(x + ((size_t)bi * 128 + h) * 128);
    float ar[8] = {}, ai[8] = {};
    for (int w4 = 0; w4 < 32; w4++) {
        float4 xv = xr4[w4];
        float xd4[4] = {xv.x, xv.y, xv.z, xv.w};
        #pragma unroll
        for (int d = 0; d < 4; d++) {
            const float4* tp = (const float4*)(tw1 + (w4 * 4 + d) * 16 + kyh);
            float xd = xd4[d];
            #pragma unroll
            for (int q = 0; q < 4; q++) {
                float4 tv = tp[q];     // two complex twiddles
                ar[2*q]   = fmaf(xd, tv.x, ar[2*q]);
                ai[2*q]   = fmaf(xd, tv.y, ai[2*q]);
                ar[2*q+1] = fmaf(xd, tv.z, ar[2*q+1]);
                ai[2*q+1] = fmaf(xd, tv.w, ai[2*q+1]);
            }
        }
    }
    #pragma unroll
    for (int k = 0; k < 8; k++)
        ys[h * 17 + kyh + k] = make_float2(ar[k], ai[k]);
    __syncthreads();

    // ---- stage 2: 512 outputs (m,ky) ----
    #pragma unroll
    for (int r = 0; r < 2; r++) {
        int idx = r * 256 + t;
        int m  = idx >> 4, ky = idx & 15;
        int kx = (m < 16) ? m : (96 + m);     // 0..15, 112..127
        float sr = 0.f, si = 0.f;
        #pragma unroll 4
        for (int hh = 0; hh < 128; hh++) {
            float2 y = ys[hh * 17 + ky];
            float2 g = Tg[(kx * hh) & 127];   // e^{-i} applied via signs below
            sr = fmaf(y.x,  g.x, sr); sr = fmaf(y.y, g.y, sr);
            si = fmaf(y.y,  g.x, si); si = fmaf(-y.x, g.y, si);
        }
        g_xft[(size_t)idx * 1024 + bi] =
            make_float2(sr * 0.0078125f, si * 0.0078125f);  // 1/sqrt(H*W)
    }
}

// ---------------------------------------------------------------------------
// K2: per-mode channel mixing. One block per mode mk, 1024 threads (b,o).
//   oft[b,o] = sum_i xft[b,i] * w[i,o]   (complex)
// ---------------------------------------------------------------------------
__global__ void __launch_bounds__(1024) k2_mix() {
    __shared__ float2 xfS[1024];
    __shared__ float2 wS[1024];
    int t  = threadIdx.x;
    int mk = blockIdx.x;
    xfS[t] = g_xft[(size_t)mk * 1024 + t];
    wS[t]  = g_wt [(size_t)mk * 1024 + t];
    __syncthreads();
    int b = t >> 5, o = t & 31;
    float orr = 0.f, oii = 0.f;
    #pragma unroll
    for (int i = 0; i < 32; i++) {
        float2 xv = xfS[b * 32 + i];
        float2 wv = wS[i * 32 + o];
        orr = fmaf(xv.x, wv.x, orr); orr = fmaf(-xv.y, wv.y, orr);
        oii = fmaf(xv.x, wv.y, oii); oii = fmaf(xv.y,  wv.x, oii);
    }
    g_oft[(size_t)t * 512 + mk] = make_float2(orr, oii);   // t == b*32+o
}

// ---------------------------------------------------------------------------
// K3: inverse. One block per (b,o).
//   stage A: A[h,ky] = sum_m oft[m,ky] * e^{+2pi i kx h / 128}
//            scaled by (ky==0 ? 1 : 2)/128   (ortho inverse + hermitian fold;
//            imag of ky=0 is dropped by irfft semantics)
//   stage B: out[h,w] = sum_ky ( Ar*cos(2pi ky w/128) - Ai*sin(...) )
// ---------------------------------------------------------------------------
__global__ void __launch_bounds__(256) k3_inverse(float* __restrict__ out) {
    __shared__ float2 ofS[512];
    __shared__ float2 Tg[128];
    __shared__ float2 As[128 * 17];      // stride 17 bank pad
    __shared__ float tw2c[2048];         // [ky][w]
    __shared__ float tw2s[2048];

    int t  = threadIdx.x;
    int bo = blockIdx.x;   // b*32+o

    for (int p = t; p < 128; p += 256) {
        float s, c;
        sincosf(PI2 * (float)p * (1.0f / 128.0f), &s, &c);
        Tg[p] = make_float2(c, s);
    }
    for (int idx = t; idx < 512; idx += 256)
        ofS[idx] = g_oft[(size_t)bo * 512 + idx];
    __syncthreads();
    for (int idx = t; idx < 2048; idx += 256) {
        int ky = idx >> 7, w = idx & 127;
        float2 g = Tg[(ky * w) & 127];
        tw2c[idx] = g.x;
        tw2s[idx] = g.y;
    }
    __syncthreads();

    // ---- stage A ----
    #pragma unroll
    for (int j = 0; j < 8; j++) {
        int idx = j * 256 + t;
        int h = idx >> 4, ky = idx & 15;
        float ar = 0.f, ai = 0.f;
        #pragma unroll
        for (int m = 0; m < 32; m++) {
            int kx = (m < 16) ? m : (96 + m);
            float2 ov = ofS[m * 16 + ky];
            float2 g  = Tg[(kx * h) & 127];     // e^{+i theta}
            ar = fmaf(ov.x, g.x, ar); ar = fmaf(-ov.y, g.y, ar);
            ai = fmaf(ov.x, g.y, ai); ai = fmaf( ov.y, g.x, ai);
        }
        float sc = (ky == 0) ? 0.0078125f : 0.015625f;   // 1/128 or 2/128
        As[h * 17 + ky] = make_float2(ar * sc, ai * sc);
    }
    __syncthreads();

    // ---- stage B: thread tile = 2 h-rows x 4 strided w ----
    float* orow = out + (size_t)bo * 16384;
    int wl = t & 31;
    int hp = t >> 5;
    for (int j = 0; j < 8; j++) {
        int h0 = (j * 8 + hp) * 2;
        float acc0[4] = {}, acc1[4] = {};
        #pragma unroll
        for (int ky = 0; ky < 16; ky++) {
            float2 a0 = As[h0 * 17 + ky];
            float2 a1 = As[(h0 + 1) * 17 + ky];
            #pragma unroll
            for (int k = 0; k < 4; k++) {
                float c = tw2c[ky * 128 + wl + 32 * k];
                float s = tw2s[ky * 128 + wl + 32 * k];
                acc0[k] = fmaf(a0.x, c, acc0[k]); acc0[k] = fmaf(-a0.y, s, acc0[k]);
                acc1[k] = fmaf(a1.x, c, acc1[k]); acc1[k] = fmaf(-a1.y, s, acc1[k]);
            }
        }
        #pragma unroll
        for (int k = 0; k < 4; k++) {
            orow[h0 * 128 + wl + 32 * k]       = acc0[k];
            orow[(h0 + 1) * 128 + wl + 32 * k] = acc1[k];
        }
    }
}

// ---------------------------------------------------------------------------
extern "C" void kernel_launch(void* const* d_in, const int* in_sizes, int n_in,
                              void* d_out, int out_size) {
    const float* x  = (const float*)d_in[0];
    const float* wr = (const float*)d_in[1];
    const float* wi = (const float*)d_in[2];
    float* out = (float*)d_out;

    k0_wt<<<2048, 256>>>(wr, wi);
    k1_forward<<<1024, 256>>>(x);
    k2_mix<<<512, 1024>>>();
    k3_inverse<<<1024, 256>>>(out);
}

// round 2
// speedup vs baseline: 1.0783x; 1.0783x over previous
#include <cuda_runtime.h>

#define PI2 6.28318530717958647692f

typedef unsigned long long u64;

__device__ __forceinline__ u64 pk2(float lo, float hi) {
    u64 r; asm("mov.b64 %0,{%1,%2};" : "=l"(r) : "f"(lo), "f"(hi)); return r;
}
__device__ __forceinline__ void fma2(u64 &d, u64 a, u64 b) {
    asm("fma.rn.f32x2 %0,%1,%2,%0;" : "+l"(d) : "l"(a), "l"(b));
}
__device__ __forceinline__ float2 upk(u64 v) {
    float2 f; asm("mov.b64 {%0,%1},%2;" : "=f"(f.x), "=f"(f.y) : "l"(v)); return f;
}

// Scratch (device globals — no allocation allowed).
// g_xft: [mode(512)][b*32+i(1024)] complex
// g_wt : [mode(512)][i*32+o(1024)] complex
// g_oft: [b*32+o(1024)][mode(512)] complex
static __device__ float2 g_xft[512 * 1024];
static __device__ float2 g_wt [512 * 1024];
static __device__ float2 g_oft[1024 * 512];

// ---------------------------------------------------------------------------
// K0: tiled transpose of weights [io][mk] -> [mk][io] (both sides coalesced)
// grid: 512 blocks = 16 mk-tiles x 32 io-tiles, 256 threads
// ---------------------------------------------------------------------------
__global__ void __launch_bounds__(256) k0_wt(const float* __restrict__ wr,
                                             const float* __restrict__ wi) {
    __shared__ float2 tile[32][33];
    int bm  = blockIdx.x & 15;    // mk tile
    int bio = blockIdx.x >> 4;    // io tile
    int mk0 = bm * 32, io0 = bio * 32;
    int c  = threadIdx.x & 31;
    int r4 = threadIdx.x >> 5;    // 0..7
    #pragma unroll
    for (int k = 0; k < 4; k++) {
        int r = r4 + 8 * k;
        size_t src = (size_t)(io0 + r) * 512 + mk0 + c;
        tile[r][c] = make_float2(wr[src], wi[src]);
    }
    __syncthreads();
    #pragma unroll
    for (int k = 0; k < 4; k++) {
        int c2 = r4 + 8 * k;      // mk within tile
        g_wt[(size_t)(mk0 + c2) * 1024 + io0 + c] = tile[c][c2];
    }
}

// ---------------------------------------------------------------------------
// K1: forward truncated DFT. One block per (b,i).
//   stage1: y[h,ky]  = sum_w  x[h,w]  * e^{-2pi i ky w / 128}   (ky = 0..15)
//   stage2: xft[m,ky]= sum_h  y[h,ky] * e^{-2pi i kx h / 128}   (kx = m<16?m:96+m)
//   scaled by 1/128 (ortho forward)
// ---------------------------------------------------------------------------
__global__ void __launch_bounds__(256, 2) k1_forward(const float* __restrict__ x) {
    __shared__ __align__(16) float twr[2048];    // cos, [w][ky]
    __shared__ __align__(16) float twi[2048];    // -sin, [w][ky]
    __shared__ float2 Tg[128];                   // (cos,sin)(2pi p/128)
    __shared__ float2 ys[128 * 17];              // y[h][ky], stride 17

    int t  = threadIdx.x;
    int bi = blockIdx.x;   // b*32+i

    for (int p = t; p < 128; p += 256) {
        float s, c;
        sincosf(PI2 * (float)p * (1.0f / 128.0f), &s, &c);
        Tg[p] = make_float2(c, s);
    }
    __syncthreads();
    for (int idx = t; idx < 2048; idx += 256) {
        int w = idx >> 4, ky = idx & 15;
        float2 g = Tg[(w * ky) & 127];
        twr[idx] = g.x;
        twi[idx] = -g.y;
    }
    __syncthreads();

    // ---- stage 1: thread owns (h = t>>1, 8 ky). f32x2 packed FMA. ----
    {
        int h   = t >> 1;
        int kyh = (t & 1) * 8;
        const float4* xr4 = (const float4*)(x + ((size_t)bi * 128 + h) * 128);
        u64 ar[4] = {0,0,0,0}, ai[4] = {0,0,0,0};   // pairs of ky
        for (int w4 = 0; w4 < 32; w4++) {
            float4 xv = xr4[w4];
            float xd4[4] = {xv.x, xv.y, xv.z, xv.w};
            #pragma unroll
            for (int d = 0; d < 4; d++) {
                int w = w4 * 4 + d;
                u64 xd2 = pk2(xd4[d], xd4[d]);
                const ulonglong2* rp = (const ulonglong2*)(twr + w * 16 + kyh);
                const ulonglong2* ip = (const ulonglong2*)(twi + w * 16 + kyh);
                ulonglong2 ra = rp[0], rb = rp[1];
                ulonglong2 ia = ip[0], ib = ip[1];
                fma2(ar[0], xd2, ra.x); fma2(ar[1], xd2, ra.y);
                fma2(ar[2], xd2, rb.x); fma2(ar[3], xd2, rb.y);
                fma2(ai[0], xd2, ia.x); fma2(ai[1], xd2, ia.y);
                fma2(ai[2], xd2, ib.x); fma2(ai[3], xd2, ib.y);
            }
        }
        #pragma unroll
        for (int q = 0; q < 4; q++) {
            float2 a = upk(ar[q]), b2 = upk(ai[q]);
            ys[h * 17 + kyh + 2 * q]     = make_float2(a.x, b2.x);
            ys[h * 17 + kyh + 2 * q + 1] = make_float2(a.y, b2.y);
        }
    }
    __syncthreads();

    // ---- stage 2: thread owns (ky = t&15, two m values) ----
    {
        int ky = t & 15, mg = t >> 4;
        int m0 = mg * 2, m1 = m0 + 1;
        int kx0 = (m0 < 16) ? m0 : (96 + m0);
        int kx1 = (m1 < 16) ? m1 : (96 + m1);
        float sr0 = 0.f, si0 = 0.f, sr1 = 0.f, si1 = 0.f;
        int i0 = 0, i1 = 0;
        #pragma unroll 4
        for (int h = 0; h < 128; h++) {
            float2 y  = ys[h * 17 + ky];
            float2 g0 = Tg[i0], g1 = Tg[i1];
            sr0 = fmaf(y.x,  g0.x, sr0); sr0 = fmaf(y.y, g0.y, sr0);
            si0 = fmaf(y.y,  g0.x, si0); si0 = fmaf(-y.x, g0.y, si0);
            sr1 = fmaf(y.x,  g1.x, sr1); sr1 = fmaf(y.y, g1.y, sr1);
            si1 = fmaf(y.y,  g1.x, si1); si1 = fmaf(-y.x, g1.y, si1);
            i0 = (i0 + kx0) & 127; i1 = (i1 + kx1) & 127;
        }
        g_xft[(size_t)(m0 * 16 + ky) * 1024 + bi] =
            make_float2(sr0 * 0.0078125f, si0 * 0.0078125f);
        g_xft[(size_t)(m1 * 16 + ky) * 1024 + bi] =
            make_float2(sr1 * 0.0078125f, si1 * 0.0078125f);
    }
}

// ---------------------------------------------------------------------------
// K2: per-mode channel mixing. One block per mode, 256 threads, 4-wide o tile.
//   oft[b,o] = sum_i xft[b,i] * w[i,o]   (complex)
// ---------------------------------------------------------------------------
__global__ void __launch_bounds__(256) k2_mix() {
    __shared__ float2 xfS[1024];
    __shared__ __align__(16) float2 wS[1024];
    int t  = threadIdx.x;
    int mk = blockIdx.x;
    for (int j = t; j < 1024; j += 256) {
        xfS[j] = g_xft[(size_t)mk * 1024 + j];
        wS[j]  = g_wt [(size_t)mk * 1024 + j];
    }
    __syncthreads();
    int b  = t >> 3;
    int o0 = (t & 7) * 4;
    float ar[4] = {}, ai[4] = {};
    #pragma unroll 8
    for (int i = 0; i < 32; i++) {
        float2 xv = xfS[b * 32 + i];
        const float4* wp = (const float4*)(wS + i * 32 + o0);
        float4 wa = wp[0], wb = wp[1];   // (r,i) x 4 o
        ar[0] = fmaf(xv.x, wa.x, ar[0]); ar[0] = fmaf(-xv.y, wa.y, ar[0]);
        ai[0] = fmaf(xv.x, wa.y, ai[0]); ai[0] = fmaf( xv.y, wa.x, ai[0]);
        ar[1] = fmaf(xv.x, wa.z, ar[1]); ar[1] = fmaf(-xv.y, wa.w, ar[1]);
        ai[1] = fmaf(xv.x, wa.w, ai[1]); ai[1] = fmaf( xv.y, wa.z, ai[1]);
        ar[2] = fmaf(xv.x, wb.x, ar[2]); ar[2] = fmaf(-xv.y, wb.y, ar[2]);
        ai[2] = fmaf(xv.x, wb.y, ai[2]); ai[2] = fmaf( xv.y, wb.x, ai[2]);
        ar[3] = fmaf(xv.x, wb.z, ar[3]); ar[3] = fmaf(-xv.y, wb.w, ar[3]);
        ai[3] = fmaf(xv.x, wb.w, ai[3]); ai[3] = fmaf( xv.y, wb.z, ai[3]);
    }
    size_t base = (size_t)(b * 32 + o0) * 512 + mk;
    #pragma unroll
    for (int k = 0; k < 4; k++)
        g_oft[base + (size_t)k * 512] = make_float2(ar[k], ai[k]);
}

// ---------------------------------------------------------------------------
// K3: inverse. One block per (b,o).
//   stage A: A[h,ky] = sum_m oft[m,ky] * e^{+2pi i kx h / 128}
//            scaled by (ky==0 ? 1 : 2)/128
//   stage B: out[h,w] = sum_ky ( Ar*cos(2pi ky w/128) - Ai*sin(...) )
// ---------------------------------------------------------------------------
__global__ void __launch_bounds__(256, 2) k3_inverse(float* __restrict__ out) {
    __shared__ float2 ofS[512];
    __shared__ float2 Tg[128];
    __shared__ float2 As[128 * 17];              // stride-17 pad
    __shared__ __align__(16) float twc[2048];    // [ky][w]
    __shared__ __align__(16) float tws[2048];

    int t  = threadIdx.x;
    int bo = blockIdx.x;   // b*32+o

    for (int p = t; p < 128; p += 256) {
        float s, c;
        sincosf(PI2 * (float)p * (1.0f / 128.0f), &s, &c);
        Tg[p] = make_float2(c, s);
    }
    for (int idx = t; idx < 512; idx += 256)
        ofS[idx] = g_oft[(size_t)bo * 512 + idx];
    __syncthreads();
    for (int idx = t; idx < 2048; idx += 256) {
        int ky = idx >> 7, w = idx & 127;
        float2 g = Tg[(ky * w) & 127];
        twc[idx] = g.x;
        tws[idx] = g.y;
    }
    __syncthreads();

    // ---- stage A: thread owns (ky = t&15, 8 h values). ofS amortized. ----
    {
        int ky = t & 15, hb = t >> 4;
        float ar[8] = {}, ai[8] = {};
        for (int m = 0; m < 32; m++) {
            int kx = (m < 16) ? m : (96 + m);
            float2 ov = ofS[m * 16 + ky];
            int idx  = (kx * hb) & 127;
            int step = (kx << 4) & 127;
            #pragma unroll
            for (int j = 0; j < 8; j++) {
                float2 g = Tg[idx];
                ar[j] = fmaf(ov.x, g.x, ar[j]); ar[j] = fmaf(-ov.y, g.y, ar[j]);
                ai[j] = fmaf(ov.x, g.y, ai[j]); ai[j] = fmaf( ov.y, g.x, ai[j]);
                idx = (idx + step) & 127;
            }
        }
        float sc = (ky == 0) ? 0.0078125f : 0.015625f;
        #pragma unroll
        for (int j = 0; j < 8; j++)
            As[(hb + 16 * j) * 17 + ky] = make_float2(ar[j] * sc, ai[j] * sc);
    }
    __syncthreads();

    // ---- stage B: thread tile = 4 h rows x 4 consecutive w. f32x2. ----
    {
        float* orow = out + (size_t)bo * 16384;
        int wq = (t & 31) * 4;
        int hg = t >> 5;
        for (int pass = 0; pass < 4; pass++) {
            int h0 = pass * 32 + hg * 4;
            u64 acc[8] = {0,0,0,0,0,0,0,0};   // [d][half]
            #pragma unroll 4
            for (int ky = 0; ky < 16; ky++) {
                ulonglong2 c2 = *(const ulonglong2*)(twc + ky * 128 + wq);
                ulonglong2 s2 = *(const ulonglong2*)(tws + ky * 128 + wq);
                #pragma unroll
                for (int d = 0; d < 4; d++) {
                    float2 a = As[(h0 + d) * 17 + ky];
                    u64 ax = pk2(a.x, a.x);
                    u64 ny = pk2(-a.y, -a.y);
                    fma2(acc[d * 2],     ax, c2.x); fma2(acc[d * 2],     ny, s2.x);
                    fma2(acc[d * 2 + 1], ax, c2.y); fma2(acc[d * 2 + 1], ny, s2.y);
                }
            }
            #pragma unroll
            for (int d = 0; d < 4; d++) {
                float2 lo = upk(acc[d * 2]), hi = upk(acc[d * 2 + 1]);
                *(float4*)(orow + (size_t)(h0 + d) * 128 + wq) =
                    make_float4(lo.x, lo.y, hi.x, hi.y);
            }
        }
    }
}

// ---------------------------------------------------------------------------
extern "C" void kernel_launch(void* const* d_in, const int* in_sizes, int n_in,
                              void* d_out, int out_size) {
    const float* x  = (const float*)d_in[0];
    const float* wr = (const float*)d_in[1];
    const float* wi = (const float*)d_in[2];
    float* out = (float*)d_out;

    k0_wt<<<512, 256>>>(wr, wi);
    k1_forward<<<1024, 256>>>(x);
    k2_mix<<<512, 256>>>();
    k3_inverse<<<1024, 256>>>(out);
}

// round 3
// speedup vs baseline: 1.0817x; 1.0031x over previous
#include <cuda_runtime.h>

#define PI2 6.28318530717958647692f

typedef unsigned long long u64;

__device__ __forceinline__ u64 pk2(float lo, float hi) {
    u64 r; asm("mov.b64 %0,{%1,%2};" : "=l"(r) : "f"(lo), "f"(hi)); return r;
}
__device__ __forceinline__ void fma2(u64 &d, u64 a, u64 b) {
    asm("fma.rn.f32x2 %0,%1,%2,%0;" : "+l"(d) : "l"(a), "l"(b));
}
__device__ __forceinline__ float2 upk(u64 v) {
    float2 f; asm("mov.b64 {%0,%1},%2;" : "=f"(f.x), "=f"(f.y) : "l"(v)); return f;
}

// Scratch (device globals — no allocation allowed).
// g_xft: [mode(512)][b*32+i(1024)] complex
// g_wt : [mode(512)][i*32+o(1024)] complex
// g_oft: [b*32+o(1024)][mode(512)] complex
static __device__ float2 g_xft[512 * 1024];
static __device__ float2 g_wt [512 * 1024];
static __device__ float2 g_oft[1024 * 512];

// ---------------------------------------------------------------------------
// K0: tiled transpose of weights [io][mk] -> [mk][io] (both sides coalesced)
// grid: 512 blocks = 16 mk-tiles x 32 io-tiles, 256 threads
// ---------------------------------------------------------------------------
__global__ void __launch_bounds__(256) k0_wt(const float* __restrict__ wr,
                                             const float* __restrict__ wi) {
    __shared__ float2 tile[32][33];
    int bm  = blockIdx.x & 15;    // mk tile
    int bio = blockIdx.x >> 4;    // io tile
    int mk0 = bm * 32, io0 = bio * 32;
    int c  = threadIdx.x & 31;
    int r4 = threadIdx.x >> 5;    // 0..7
    #pragma unroll
    for (int k = 0; k < 4; k++) {
        int r = r4 + 8 * k;
        size_t src = (size_t)(io0 + r) * 512 + mk0 + c;
        tile[r][c] = make_float2(wr[src], wi[src]);
    }
    __syncthreads();
    #pragma unroll
    for (int k = 0; k < 4; k++) {
        int c2 = r4 + 8 * k;      // mk within tile
        g_wt[(size_t)(mk0 + c2) * 1024 + io0 + c] = tile[c][c2];
    }
}

// ---------------------------------------------------------------------------
// K1: forward truncated DFT. One block per (b,i).
//   stage1: y[h,ky]  = sum_w  x[h,w]  * e^{-2pi i ky w / 128}   (ky = 0..15)
//   stage2: xft[m,ky]= sum_h  y[h,ky] * e^{-2pi i kx h / 128}   (kx = m<16?m:96+m)
//   scaled by 1/128 (ortho forward)
// ---------------------------------------------------------------------------
__global__ void __launch_bounds__(256, 2) k1_forward(const float* __restrict__ x) {
    __shared__ __align__(16) float twr[2048];    // cos, [w][ky]
    __shared__ __align__(16) float twi[2048];    // -sin, [w][ky]
    __shared__ float2 Tg[128];                   // (cos,sin)(2pi p/128)
    __shared__ float2 ys[128 * 17];              // y[h][ky], stride 17

    int t  = threadIdx.x;
    int bi = blockIdx.x;   // b*32+i

    for (int p = t; p < 128; p += 256) {
        float s, c;
        sincosf(PI2 * (float)p * (1.0f / 128.0f), &s, &c);
        Tg[p] = make_float2(c, s);
    }
    __syncthreads();
    for (int idx = t; idx < 2048; idx += 256) {
        int w = idx >> 4, ky = idx & 15;
        float2 g = Tg[(w * ky) & 127];
        twr[idx] = g.x;
        twi[idx] = -g.y;
    }
    __syncthreads();

    // ---- stage 1: thread owns (h = t>>1, 8 ky). f32x2 packed FMA. ----
    {
        int h   = t >> 1;
        int kyh = (t & 1) * 8;
        const float4* xr4 = (const float4*)(x + ((size_t)bi * 128 + h) * 128);
        u64 ar[4] = {0,0,0,0}, ai[4] = {0,0,0,0};   // pairs of ky
        for (int w4 = 0; w4 < 32; w4++) {
            float4 xv = xr4[w4];
            float xd4[4] = {xv.x, xv.y, xv.z, xv.w};
            #pragma unroll
            for (int d = 0; d < 4; d++) {
                int w = w4 * 4 + d;
                u64 xd2 = pk2(xd4[d], xd4[d]);
                const ulonglong2* rp = (const ulonglong2*)(twr + w * 16 + kyh);
                const ulonglong2* ip = (const ulonglong2*)(twi + w * 16 + kyh);
                ulonglong2 ra = rp[0], rb = rp[1];
                ulonglong2 ia = ip[0], ib = ip[1];
                fma2(ar[0], xd2, ra.x); fma2(ar[1], xd2, ra.y);
                fma2(ar[2], xd2, rb.x); fma2(ar[3], xd2, rb.y);
                fma2(ai[0], xd2, ia.x); fma2(ai[1], xd2, ia.y);
                fma2(ai[2], xd2, ib.x); fma2(ai[3], xd2, ib.y);
            }
        }
        #pragma unroll
        for (int q = 0; q < 4; q++) {
            float2 a = upk(ar[q]), b2 = upk(ai[q]);
            ys[h * 17 + kyh + 2 * q]     = make_float2(a.x, b2.x);
            ys[h * 17 + kyh + 2 * q + 1] = make_float2(a.y, b2.y);
        }
    }
    __syncthreads();

    // ---- stage 2: thread owns (ky = t&15, two m values) ----
    {
        int ky = t & 15, mg = t >> 4;
        int m0 = mg * 2, m1 = m0 + 1;
        int kx0 = (m0 < 16) ? m0 : (96 + m0);
        int kx1 = (m1 < 16) ? m1 : (96 + m1);
        float sr0 = 0.f, si0 = 0.f, sr1 = 0.f, si1 = 0.f;
        int i0 = 0, i1 = 0;
        #pragma unroll 4
        for (int h = 0; h < 128; h++) {
            float2 y  = ys[h * 17 + ky];
            float2 g0 = Tg[i0], g1 = Tg[i1];
            sr0 = fmaf(y.x,  g0.x, sr0); sr0 = fmaf(y.y, g0.y, sr0);
            si0 = fmaf(y.y,  g0.x, si0); si0 = fmaf(-y.x, g0.y, si0);
            sr1 = fmaf(y.x,  g1.x, sr1); sr1 = fmaf(y.y, g1.y, sr1);
            si1 = fmaf(y.y,  g1.x, si1); si1 = fmaf(-y.x, g1.y, si1);
            i0 = (i0 + kx0) & 127; i1 = (i1 + kx1) & 127;
        }
        g_xft[(size_t)(m0 * 16 + ky) * 1024 + bi] =
            make_float2(sr0 * 0.0078125f, si0 * 0.0078125f);
        g_xft[(size_t)(m1 * 16 + ky) * 1024 + bi] =
            make_float2(sr1 * 0.0078125f, si1 * 0.0078125f);
    }
}

// ---------------------------------------------------------------------------
// K2: per-mode channel mixing. One block per mode, 256 threads, 4-wide o tile.
//   oft[b,o] = sum_i xft[b,i] * w[i,o]   (complex)
// ---------------------------------------------------------------------------
__global__ void __launch_bounds__(256) k2_mix() {
    __shared__ float2 xfS[1024];
    __shared__ __align__(16) float2 wS[1024];
    int t  = threadIdx.x;
    int mk = blockIdx.x;
    for (int j = t; j < 1024; j += 256) {
        xfS[j] = g_xft[(size_t)mk * 1024 + j];
        wS[j]  = g_wt [(size_t)mk * 1024 + j];
    }
    __syncthreads();
    int b  = t >> 3;
    int o0 = (t & 7) * 4;
    float ar[4] = {}, ai[4] = {};
    #pragma unroll 8
    for (int i = 0; i < 32; i++) {
        float2 xv = xfS[b * 32 + i];
        const float4* wp = (const float4*)(wS + i * 32 + o0);
        float4 wa = wp[0], wb = wp[1];   // (r,i) x 4 o
        ar[0] = fmaf(xv.x, wa.x, ar[0]); ar[0] = fmaf(-xv.y, wa.y, ar[0]);
        ai[0] = fmaf(xv.x, wa.y, ai[0]); ai[0] = fmaf( xv.y, wa.x, ai[0]);
        ar[1] = fmaf(xv.x, wa.z, ar[1]); ar[1] = fmaf(-xv.y, wa.w, ar[1]);
        ai[1] = fmaf(xv.x, wa.w, ai[1]); ai[1] = fmaf( xv.y, wa.z, ai[1]);
        ar[2] = fmaf(xv.x, wb.x, ar[2]); ar[2] = fmaf(-xv.y, wb.y, ar[2]);
        ai[2] = fmaf(xv.x, wb.y, ai[2]); ai[2] = fmaf( xv.y, wb.x, ai[2]);
        ar[3] = fmaf(xv.x, wb.z, ar[3]); ar[3] = fmaf(-xv.y, wb.w, ar[3]);
        ai[3] = fmaf(xv.x, wb.w, ai[3]); ai[3] = fmaf( xv.y, wb.z, ai[3]);
    }
    size_t base = (size_t)(b * 32 + o0) * 512 + mk;
    #pragma unroll
    for (int k = 0; k < 4; k++)
        g_oft[base + (size_t)k * 512] = make_float2(ar[k], ai[k]);
}

// ---------------------------------------------------------------------------
// K3: inverse. One block per (b,o).
//   stage A: A[h,ky] = sum_m oft[m,ky] * e^{+2pi i kx h / 128}
//            scaled by (ky==0 ? 1 : 2)/128
//   stage B: out[h,w] = sum_ky ( Ar*cos(2pi ky w/128) - Ai*sin(...) )
// ---------------------------------------------------------------------------
__global__ void __launch_bounds__(256, 2) k3_inverse(float* __restrict__ out) {
    __shared__ float2 ofS[512];
    __shared__ float2 Tg[128];
    __shared__ float2 As[128 * 17];              // stride-17 pad
    __shared__ __align__(16) float twc[2048];    // [ky][w]
    __shared__ __align__(16) float tws[2048];

    int t  = threadIdx.x;
    int bo = blockIdx.x;   // b*32+o

    for (int p = t; p < 128; p += 256) {
        float s, c;
        sincosf(PI2 * (float)p * (1.0f / 128.0f), &s, &c);
        Tg[p] = make_float2(c, s);
    }
    for (int idx = t; idx < 512; idx += 256)
        ofS[idx] = g_oft[(size_t)bo * 512 + idx];
    __syncthreads();
    for (int idx = t; idx < 2048; idx += 256) {
        int ky = idx >> 7, w = idx & 127;
        float2 g = Tg[(ky * w) & 127];
        twc[idx] = g.x;
        tws[idx] = g.y;
    }
    __syncthreads();

    // ---- stage A: thread owns (ky = t&15, 8 h values). ofS amortized. ----
    {
        int ky = t & 15, hb = t >> 4;
        float ar[8] = {}, ai[8] = {};
        for (int m = 0; m < 32; m++) {
            int kx = (m < 16) ? m : (96 + m);
            float2 ov = ofS[m * 16 + ky];
            int idx  = (kx * hb) & 127;
            int step = (kx << 4) & 127;
            #pragma unroll
            for (int j = 0; j < 8; j++) {
                float2 g = Tg[idx];
                ar[j] = fmaf(ov.x, g.x, ar[j]); ar[j] = fmaf(-ov.y, g.y, ar[j]);
                ai[j] = fmaf(ov.x, g.y, ai[j]); ai[j] = fmaf( ov.y, g.x, ai[j]);
                idx = (idx + step) & 127;
            }
        }
        float sc = (ky == 0) ? 0.0078125f : 0.015625f;
        #pragma unroll
        for (int j = 0; j < 8; j++)
            As[(hb + 16 * j) * 17 + ky] = make_float2(ar[j] * sc, ai[j] * sc);
    }
    __syncthreads();

    // ---- stage B: thread tile = 4 h rows x 4 consecutive w. f32x2. ----
    {
        float* orow = out + (size_t)bo * 16384;
        int wq = (t & 31) * 4;
        int hg = t >> 5;
        for (int pass = 0; pass < 4; pass++) {
            int h0 = pass * 32 + hg * 4;
            u64 acc[8] = {0,0,0,0,0,0,0,0};   // [d][half]
            #pragma unroll 4
            for (int ky = 0; ky < 16; ky++) {
                ulonglong2 c2 = *(const ulonglong2*)(twc + ky * 128 + wq);
                ulonglong2 s2 = *(const ulonglong2*)(tws + ky * 128 + wq);
                #pragma unroll
                for (int d = 0; d < 4; d++) {
                    float2 a = As[(h0 + d) * 17 + ky];
                    u64 ax = pk2(a.x, a.x);
                    u64 ny = pk2(-a.y, -a.y);
                    fma2(acc[d * 2],     ax, c2.x); fma2(acc[d * 2],     ny, s2.x);
                    fma2(acc[d * 2 + 1], ax, c2.y); fma2(acc[d * 2 + 1], ny, s2.y);
                }
            }
            #pragma unroll
            for (int d = 0; d < 4; d++) {
                float2 lo = upk(acc[d * 2]), hi = upk(acc[d * 2 + 1]);
                *(float4*)(orow + (size_t)(h0 + d) * 128 + wq) =
                    make_float4(lo.x, lo.y, hi.x, hi.y);
            }
        }
    }
}

// ---------------------------------------------------------------------------
extern "C" void kernel_launch(void* const* d_in, const int* in_sizes, int n_in,
                              void* d_out, int out_size) {
    const float* x  = (const float*)d_in[0];
    const float* wr = (const float*)d_in[1];
    const float* wi = (const float*)d_in[2];
    float* out = (float*)d_out;

    k0_wt<<<512, 256>>>(wr, wi);
    k1_forward<<<1024, 256>>>(x);
    k2_mix<<<512, 256>>>();
    k3_inverse<<<1024, 256>>>(out);
}